// round 5
// baseline (speedup 1.0000x reference)
#include <cuda_runtime.h>
#include <math.h>

// ---------------------------------------------------------------------------
// Problem constants
// ---------------------------------------------------------------------------
#define BATCH 4
#define SEQ   2048
#define HID   2048
#define NHEAD 16
#define HD    128
#define RNK   64
#define IDXD  512
#define NIDX  65536
#define TOPK  4
#define NTOK  512          // only first 512 tokens/batch ever attended in adapter

// ---------------------------------------------------------------------------
// Scratch (device globals; no allocation allowed)
// ---------------------------------------------------------------------------
__device__ float g_Q[(size_t)BATCH * SEQ * HID];
__device__ float g_K[(size_t)BATCH * SEQ * HID];
__device__ float g_V[(size_t)BATCH * SEQ * HID];
__device__ float g_attn[(size_t)BATCH * SEQ * HID];
__device__ float g_scores[(size_t)BATCH * NHEAD * SEQ * SEQ];   // 1.07 GB
__device__ float g_t1[(size_t)BATCH * SEQ * RNK];
__device__ float g_query[(size_t)BATCH * SEQ * IDXD];
__device__ float g_sim[(size_t)BATCH * NTOK * NIDX];            // 537 MB
__device__ int   g_topidx[BATCH * NTOK * TOPK];
__device__ float g_aK[(size_t)BATCH * SEQ * IDXD];
__device__ float g_aV[(size_t)BATCH * SEQ * IDXD];
__device__ float g_sc2[(size_t)BATCH * SEQ * SEQ];
__device__ float g_mome[(size_t)BATCH * SEQ * IDXD];
__device__ float g_t2[(size_t)BATCH * SEQ * RNK];

// ---------------------------------------------------------------------------
// Generic tiled SGEMM (exact fp32):  C = alpha * A * op(B) + beta * C
//   A: [M, K] row-major (lda)
//   TB=true : B is [N, K] row-major (ldb)  -> C = A * B^T
//   TB=false: B is [K, N] row-major (ldb)  -> C = A * B
// Batched over grid.z with two-level (b = z/nh, h = z%nh) offsets.
// causal_skip: skip output tiles entirely above the diagonal (scores GEMM).
// k_limit:     clamp K to row0+128 (AV GEMM with zeroed masked probs).
// ---------------------------------------------------------------------------
template<bool TB>
__global__ __launch_bounds__(256)
void gemm_tile(int M, int N, int Kd, float alpha, float beta,
               const float* __restrict__ A, int lda, long sAb, long sAh,
               const float* __restrict__ B, int ldb, long sBb, long sBh,
               float* __restrict__ C, int ldc, long sCb, long sCh,
               int nh, int causal_skip, int k_limit)
{
    int z  = blockIdx.z;
    int bb = z / nh, hh = z - bb * nh;
    A += (long)bb * sAb + (long)hh * sAh;
    B += (long)bb * sBb + (long)hh * sBh;
    C += (long)bb * sCb + (long)hh * sCh;

    int row0 = blockIdx.y << 7;
    int col0 = blockIdx.x << 7;
    if (causal_skip && col0 > row0 + 127) return;

    int kEff = Kd;
    if (k_limit) { int lim = row0 + 128; if (lim < kEff) kEff = lim; }

    __shared__ float As[8][132];   // padded: conflict-free transposed stores
    __shared__ float Bs[8][132];

    int tid = threadIdx.x;
    int tx = tid & 15, ty = tid >> 4;

    float acc[8][8];
#pragma unroll
    for (int i = 0; i < 8; i++)
#pragma unroll
        for (int j = 0; j < 8; j++) acc[i][j] = 0.f;

    for (int k0 = 0; k0 < kEff; k0 += 8) {
        // load A tile (128 rows x 8 k), store transposed As[k][m]
#pragma unroll
        for (int l = 0; l < 4; l++) {
            int idx = tid + (l << 8);
            int m = idx >> 3, k = idx & 7;
            int gm = row0 + m, gk = k0 + k;
            float v = 0.f;
            if (gm < M && gk < Kd) v = A[(long)gm * lda + gk];
            As[k][m] = v;
        }
        // load B tile -> Bs[k][n]
#pragma unroll
        for (int l = 0; l < 4; l++) {
            int idx = tid + (l << 8);
            if (TB) {
                int n = idx >> 3, k = idx & 7;
                int gn = col0 + n, gk = k0 + k;
                float v = 0.f;
                if (gn < N && gk < Kd) v = B[(long)gn * ldb + gk];
                Bs[k][n] = v;
            } else {
                int k = idx >> 7, n = idx & 127;
                int gk = k0 + k, gn = col0 + n;
                float v = 0.f;
                if (gk < Kd && gn < N) v = B[(long)gk * ldb + gn];
                Bs[k][n] = v;
            }
        }
        __syncthreads();

#pragma unroll
        for (int kk = 0; kk < 8; kk++) {
            float a[8], b[8];
            *(float4*)&a[0] = *(const float4*)&As[kk][(ty << 3) + 0];
            *(float4*)&a[4] = *(const float4*)&As[kk][(ty << 3) + 4];
            *(float4*)&b[0] = *(const float4*)&Bs[kk][(tx << 3) + 0];
            *(float4*)&b[4] = *(const float4*)&Bs[kk][(tx << 3) + 4];
#pragma unroll
            for (int i = 0; i < 8; i++)
#pragma unroll
                for (int j = 0; j < 8; j++)
                    acc[i][j] = fmaf(a[i], b[j], acc[i][j]);
        }
        __syncthreads();
    }

#pragma unroll
    for (int i = 0; i < 8; i++) {
        int gm = row0 + (ty << 3) + i;
        if (gm >= M) continue;
#pragma unroll
        for (int j = 0; j < 8; j++) {
            int gn = col0 + (tx << 3) + j;
            if (gn >= N) continue;
            long off = (long)gm * ldc + gn;
            float r = alpha * acc[i][j];
            if (beta != 0.f) r += beta * C[off];
            C[off] = r;
        }
    }
}

// ---------------------------------------------------------------------------
// fp64-accumulated GEMM (C = A * B^T), A:[M,K] lda, B:[N,K] ldb, C:[M,N] ldc.
// Batched over grid.z (stride sAb / sCb; B shared). Used for the top-k-
// sensitive chain (t1, query, sim) so selection inputs are exactly rounded.
// Tile 64x64, 256 threads, 4x4 per thread, double accumulators.
// ---------------------------------------------------------------------------
__global__ __launch_bounds__(256)
void gemm_f64acc(int M, int N, int Kd,
                 const float* __restrict__ A, int lda, long sAb,
                 const float* __restrict__ B, int ldb,
                 float* __restrict__ C, int ldc, long sCb)
{
    int b = blockIdx.z;
    A += (long)b * sAb;
    C += (long)b * sCb;

    int row0 = blockIdx.y << 6;
    int col0 = blockIdx.x << 6;

    __shared__ float As[8][68];
    __shared__ float Bs[8][68];

    int tid = threadIdx.x;
    int tx = tid & 15, ty = tid >> 4;

    double acc[4][4];
#pragma unroll
    for (int i = 0; i < 4; i++)
#pragma unroll
        for (int j = 0; j < 4; j++) acc[i][j] = 0.0;

    for (int k0 = 0; k0 < Kd; k0 += 8) {
        // 64 rows x 8 k = 512 elems; 256 threads -> 2 each
#pragma unroll
        for (int l = 0; l < 2; l++) {
            int idx = tid + (l << 8);
            int m = idx >> 3, k = idx & 7;
            int gm = row0 + m, gk = k0 + k;
            As[k][m] = (gm < M && gk < Kd) ? A[(long)gm * lda + gk] : 0.f;
            int gn = col0 + m;
            Bs[k][m] = (gn < N && gk < Kd) ? B[(long)gn * ldb + gk] : 0.f;
        }
        __syncthreads();

#pragma unroll
        for (int kk = 0; kk < 8; kk++) {
            float a[4], bb[4];
#pragma unroll
            for (int i = 0; i < 4; i++) a[i]  = As[kk][(ty << 2) + i];
#pragma unroll
            for (int j = 0; j < 4; j++) bb[j] = Bs[kk][(tx << 2) + j];
#pragma unroll
            for (int i = 0; i < 4; i++)
#pragma unroll
                for (int j = 0; j < 4; j++)
                    acc[i][j] = fma((double)a[i], (double)bb[j], acc[i][j]);
        }
        __syncthreads();
    }

#pragma unroll
    for (int i = 0; i < 4; i++) {
        int gm = row0 + (ty << 2) + i;
        if (gm >= M) continue;
#pragma unroll
        for (int j = 0; j < 4; j++) {
            int gn = col0 + (tx << 2) + j;
            if (gn >= N) continue;
            C[(long)gm * ldc + gn] = (float)acc[i][j];
        }
    }
}

// ---------------------------------------------------------------------------
// Causal row softmax on S[row, :T]; valid cols j <= q (q = row % L).
// Masked cols written as exact 0 (matches exp(finfo.min - max) == 0).
// ---------------------------------------------------------------------------
__global__ void causal_softmax_k(float* __restrict__ S, int L, int T)
{
    long row = blockIdx.x;
    int q = (int)(row % L);
    float* p = S + row * (long)T;
    int n = q + 1;
    int tid = threadIdx.x;
    __shared__ float red[32];

    float m = -INFINITY;
    for (int j = tid; j < n; j += blockDim.x) m = fmaxf(m, p[j]);
#pragma unroll
    for (int o = 16; o; o >>= 1) m = fmaxf(m, __shfl_xor_sync(0xffffffffu, m, o));
    if ((tid & 31) == 0) red[tid >> 5] = m;
    __syncthreads();
    if (tid < 32) {
        float v = (tid < (int)(blockDim.x >> 5)) ? red[tid] : -INFINITY;
#pragma unroll
        for (int o = 16; o; o >>= 1) v = fmaxf(v, __shfl_xor_sync(0xffffffffu, v, o));
        if (tid == 0) red[0] = v;
    }
    __syncthreads();
    m = red[0];
    __syncthreads();

    float s = 0.f;
    for (int j = tid; j < n; j += blockDim.x) {
        float e = expf(p[j] - m);
        p[j] = e;
        s += e;
    }
#pragma unroll
    for (int o = 16; o; o >>= 1) s += __shfl_xor_sync(0xffffffffu, s, o);
    if ((tid & 31) == 0) red[tid >> 5] = s;
    __syncthreads();
    if (tid < 32) {
        float v = (tid < (int)(blockDim.x >> 5)) ? red[tid] : 0.f;
#pragma unroll
        for (int o = 16; o; o >>= 1) v += __shfl_xor_sync(0xffffffffu, v, o);
        if (tid == 0) red[0] = v;
    }
    __syncthreads();
    float inv = 1.f / red[0];
    for (int j = tid; j < n; j += blockDim.x) p[j] *= inv;
    for (int j = n + tid; j < T; j += blockDim.x) p[j] = 0.f;
}

// ---------------------------------------------------------------------------
// Exact top-4 per row of sim[rows, NIDX]; tie-break: lower index first
// (matches jax.lax.top_k ordering).
// ---------------------------------------------------------------------------
__global__ void topk4_k(const float* __restrict__ sim, int* __restrict__ out)
{
    long row = blockIdx.x;
    const float* p = sim + row * (long)NIDX;
    int tid = threadIdx.x;   // 256

    float v0 = -INFINITY, v1 = -INFINITY, v2 = -INFINITY, v3 = -INFINITY;
    int   i0 = 0x7fffffff, i1 = 0x7fffffff, i2 = 0x7fffffff, i3 = 0x7fffffff;

    for (int j = tid; j < NIDX; j += 256) {
        float x = p[j];
        if (x > v3 || (x == v3 && j < i3)) {
            if (x > v0 || (x == v0 && j < i0)) {
                v3 = v2; i3 = i2; v2 = v1; i2 = i1; v1 = v0; i1 = i0; v0 = x; i0 = j;
            } else if (x > v1 || (x == v1 && j < i1)) {
                v3 = v2; i3 = i2; v2 = v1; i2 = i1; v1 = x; i1 = j;
            } else if (x > v2 || (x == v2 && j < i2)) {
                v3 = v2; i3 = i2; v2 = x; i2 = j;
            } else {
                v3 = x; i3 = j;
            }
        }
    }

    __shared__ float sv[1024];
    __shared__ int   si[1024];
    sv[tid * 4 + 0] = v0; si[tid * 4 + 0] = i0;
    sv[tid * 4 + 1] = v1; si[tid * 4 + 1] = i1;
    sv[tid * 4 + 2] = v2; si[tid * 4 + 2] = i2;
    sv[tid * 4 + 3] = v3; si[tid * 4 + 3] = i3;
    __syncthreads();

    if (tid == 0) {
        for (int r = 0; r < TOPK; r++) {
            float best = -INFINITY; int bid = 0x7fffffff; int bp = -1;
            for (int i = 0; i < 1024; i++) {
                float x = sv[i];
                if (x > best || (x == best && si[i] < bid)) { best = x; bid = si[i]; bp = i; }
            }
            out[row * TOPK + r] = bid;
            sv[bp] = -INFINITY; si[bp] = 0x7fffffff;
        }
    }
}

// ---------------------------------------------------------------------------
// Gather adapter K/V rows: aK[b, j, :] = index_keys[top_idx[b, j/4, j%4]]
// ---------------------------------------------------------------------------
__global__ void gather_k(const int* __restrict__ tidx,
                         const float* __restrict__ keys,
                         const float* __restrict__ vals,
                         float* __restrict__ aK, float* __restrict__ aV)
{
    int blk = blockIdx.x;              // b*2048 + j
    int b = blk >> 11;
    int j = blk & 2047;
    int id = tidx[((b * NTOK + (j >> 2)) << 2) + (j & 3)];
    const float4* ks = (const float4*)(keys + (long)id * IDXD);
    const float4* vs = (const float4*)(vals + (long)id * IDXD);
    float4* dk = (float4*)(aK + (long)blk * IDXD);
    float4* dv = (float4*)(aV + (long)blk * IDXD);
    int t = threadIdx.x;               // 128 threads * float4 = 512 floats
    dk[t] = ks[t];
    dv[t] = vs[t];
}

// ---------------------------------------------------------------------------
// Host launch
// ---------------------------------------------------------------------------
extern "C" void kernel_launch(void* const* d_in, const int* in_sizes, int n_in,
                              void* d_out, int out_size)
{
    const float* hs    = (const float*)d_in[0];
    const float* Wq    = (const float*)d_in[1];
    const float* Wk    = (const float*)d_in[2];
    const float* Wv    = (const float*)d_in[3];
    const float* Wo    = (const float*)d_in[4];
    const float* q_in  = (const float*)d_in[5];
    const float* q_out = (const float*)d_in[6];
    const float* v_in  = (const float*)d_in[7];
    const float* v_out = (const float*)d_in[8];
    const float* ikeys = (const float*)d_in[9];
    const float* ivals = (const float*)d_in[10];
    float* out = (float*)d_out;

    void* p;
    cudaGetSymbolAddress(&p, g_Q);      float* Qb   = (float*)p;
    cudaGetSymbolAddress(&p, g_K);      float* Kb   = (float*)p;
    cudaGetSymbolAddress(&p, g_V);      float* Vb   = (float*)p;
    cudaGetSymbolAddress(&p, g_attn);   float* Ab   = (float*)p;
    cudaGetSymbolAddress(&p, g_scores); float* Sb   = (float*)p;
    cudaGetSymbolAddress(&p, g_t1);     float* t1   = (float*)p;
    cudaGetSymbolAddress(&p, g_query);  float* qry  = (float*)p;
    cudaGetSymbolAddress(&p, g_sim);    float* simb = (float*)p;
    cudaGetSymbolAddress(&p, g_topidx); int*   topi = (int*)p;
    cudaGetSymbolAddress(&p, g_aK);     float* aK   = (float*)p;
    cudaGetSymbolAddress(&p, g_aV);     float* aV   = (float*)p;
    cudaGetSymbolAddress(&p, g_sc2);    float* sc2  = (float*)p;
    cudaGetSymbolAddress(&p, g_mome);   float* mome = (float*)p;
    cudaGetSymbolAddress(&p, g_t2);     float* t2   = (float*)p;

    const int MS = BATCH * SEQ;                        // 8192
    const float scale_base = 1.0f / sqrtf((float)HD);  // 1/sqrt(128)
    const float scale_adpt = 1.0f / sqrtf((float)IDXD);// 1/sqrt(512)
    dim3 blk(256);

    // 1) Q/K/V projections: [8192,2048] = hs @ W^T
    gemm_tile<true><<<dim3(HID / 128, MS / 128, 1), blk>>>(MS, HID, HID, 1.f, 0.f,
        hs, HID, 0, 0, Wq, HID, 0, 0, Qb, HID, 0, 0, 1, 0, 0);
    gemm_tile<true><<<dim3(HID / 128, MS / 128, 1), blk>>>(MS, HID, HID, 1.f, 0.f,
        hs, HID, 0, 0, Wk, HID, 0, 0, Kb, HID, 0, 0, 1, 0, 0);
    gemm_tile<true><<<dim3(HID / 128, MS / 128, 1), blk>>>(MS, HID, HID, 1.f, 0.f,
        hs, HID, 0, 0, Wv, HID, 0, 0, Vb, HID, 0, 0, 1, 0, 0);

    // 2) base scores (batched over b,h), causal tile-skip
    gemm_tile<true><<<dim3(SEQ / 128, SEQ / 128, BATCH * NHEAD), blk>>>(
        SEQ, SEQ, HD, scale_base, 0.f,
        Qb, HID, (long)SEQ * HID, HD,
        Kb, HID, (long)SEQ * HID, HD,
        Sb, SEQ, (long)NHEAD * SEQ * SEQ, (long)SEQ * SEQ,
        NHEAD, 1, 0);

    // 3) causal softmax
    causal_softmax_k<<<BATCH * NHEAD * SEQ, 256>>>(Sb, SEQ, SEQ);

    // 4) AV: attn_out = P @ V (NN, causal K-limit)
    gemm_tile<false><<<dim3(1, SEQ / 128, BATCH * NHEAD), blk>>>(
        SEQ, HD, SEQ, 1.f, 0.f,
        Sb, SEQ, (long)NHEAD * SEQ * SEQ, (long)SEQ * SEQ,
        Vb, HID, (long)SEQ * HID, HD,
        Ab, HID, (long)SEQ * HID, HD,
        NHEAD, 0, 1);

    // 5) out = attn_out @ Wo^T
    gemm_tile<true><<<dim3(HID / 128, MS / 128, 1), blk>>>(MS, HID, HID, 1.f, 0.f,
        Ab, HID, 0, 0, Wo, HID, 0, 0, out, HID, 0, 0, 1, 0, 0);

    // 6) t1 = hs @ q_in^T   [8192,64]  (fp64 accumulate: feeds top-k chain)
    gemm_f64acc<<<dim3(RNK / 64, MS / 64, 1), blk>>>(MS, RNK, HID,
        hs, HID, 0, q_in, HID, t1, RNK, 0);

    // 7) query = t1 @ q_out^T   [8192,512]  (fp64 accumulate)
    gemm_f64acc<<<dim3(IDXD / 64, MS / 64, 1), blk>>>(MS, IDXD, RNK,
        t1, RNK, 0, q_out, RNK, qry, IDXD, 0);

    // 8) sim = query[:512 tokens/batch] @ index_keys^T  (fp64 accumulate,
    //    batched over b) — exactness here prevents top-k selection flips
    gemm_f64acc<<<dim3(NIDX / 64, NTOK / 64, BATCH), blk>>>(NTOK, NIDX, IDXD,
        qry, IDXD, (long)SEQ * IDXD, ikeys, IDXD, simb, NIDX, (long)NTOK * NIDX);

    // 9) top-4 per row
    topk4_k<<<BATCH * NTOK, 256>>>(simb, topi);

    // 10) gather adapter K/V
    gather_k<<<BATCH * SEQ, 128>>>(topi, ikeys, ivals, aK, aV);

    // 11) adapter scores = query @ aK^T (batched over b, causal tile-skip)
    gemm_tile<true><<<dim3(SEQ / 128, SEQ / 128, BATCH), blk>>>(
        SEQ, SEQ, IDXD, scale_adpt, 0.f,
        qry, IDXD, (long)SEQ * IDXD, 0,
        aK, IDXD, (long)SEQ * IDXD, 0,
        sc2, SEQ, (long)SEQ * SEQ, 0,
        1, 1, 0);

    // 12) causal softmax
    causal_softmax_k<<<BATCH * SEQ, 256>>>(sc2, SEQ, SEQ);

    // 13) mome_attn = P @ aV (NN, causal K-limit)
    gemm_tile<false><<<dim3(IDXD / 128, SEQ / 128, BATCH), blk>>>(
        SEQ, IDXD, SEQ, 1.f, 0.f,
        sc2, SEQ, (long)SEQ * SEQ, 0,
        aV, IDXD, (long)SEQ * IDXD, 0,
        mome, IDXD, (long)SEQ * IDXD, 0,
        1, 0, 1);

    // 14) t2 = mome @ v_in^T   [8192,64]
    gemm_tile<true><<<dim3(1, MS / 128, 1), blk>>>(MS, RNK, IDXD, 1.f, 0.f,
        mome, IDXD, 0, 0, v_in, IDXD, 0, 0, t2, RNK, 0, 0, 1, 0, 0);

    // 15) out += R * (t2 @ v_out^T)
    gemm_tile<true><<<dim3(HID / 128, MS / 128, 1), blk>>>(MS, HID, RNK,
        (float)RNK, 1.f,
        t2, RNK, 0, 0, v_out, RNK, 0, 0, out, HID, 0, 0, 1, 0, 0);
}

// round 6
// speedup vs baseline: 9.2403x; 9.2403x over previous
#include <cuda_runtime.h>
#include <math.h>

// ---------------------------------------------------------------------------
// Problem constants
// ---------------------------------------------------------------------------
#define BATCH 4
#define SEQ   2048
#define HID   2048
#define NHEAD 16
#define HD    128
#define RNK   64
#define IDXD  512
#define NIDX  65536
#define TOPK  4
#define NTOK  512          // only first 512 tokens/batch ever attended in adapter

// ---------------------------------------------------------------------------
// Scratch (device globals; no allocation allowed)
// ---------------------------------------------------------------------------
__device__ float g_Q[(size_t)BATCH * SEQ * HID];
__device__ float g_K[(size_t)BATCH * SEQ * HID];
__device__ float g_V[(size_t)BATCH * SEQ * HID];
__device__ float g_attn[(size_t)BATCH * SEQ * HID];
__device__ float g_scores[(size_t)BATCH * NHEAD * SEQ * SEQ];   // 1.07 GB
__device__ float g_t1[(size_t)BATCH * SEQ * RNK];
__device__ float g_query[(size_t)BATCH * SEQ * IDXD];
__device__ float g_sim[(size_t)BATCH * NTOK * NIDX];            // 537 MB (fp32)
__device__ int   g_topidx[BATCH * NTOK * TOPK];
__device__ float g_aK[(size_t)BATCH * SEQ * IDXD];
__device__ float g_aV[(size_t)BATCH * SEQ * IDXD];
__device__ float g_sc2[(size_t)BATCH * SEQ * SEQ];
__device__ float g_mome[(size_t)BATCH * SEQ * IDXD];
__device__ float g_t2[(size_t)BATCH * SEQ * RNK];

// ---------------------------------------------------------------------------
// Generic tiled SGEMM (exact fp32):  C = alpha * A * op(B) + beta * C
//   A: [M, K] row-major (lda)
//   TB=true : B is [N, K] row-major (ldb)  -> C = A * B^T
//   TB=false: B is [K, N] row-major (ldb)  -> C = A * B
// Batched over grid.z with two-level (b = z/nh, h = z%nh) offsets.
// causal_skip: skip output tiles entirely above the diagonal (scores GEMM).
// k_limit:     clamp K to row0+128 (AV GEMM with zeroed masked probs).
// ---------------------------------------------------------------------------
template<bool TB>
__global__ __launch_bounds__(256)
void gemm_tile(int M, int N, int Kd, float alpha, float beta,
               const float* __restrict__ A, int lda, long sAb, long sAh,
               const float* __restrict__ B, int ldb, long sBb, long sBh,
               float* __restrict__ C, int ldc, long sCb, long sCh,
               int nh, int causal_skip, int k_limit)
{
    int z  = blockIdx.z;
    int bb = z / nh, hh = z - bb * nh;
    A += (long)bb * sAb + (long)hh * sAh;
    B += (long)bb * sBb + (long)hh * sBh;
    C += (long)bb * sCb + (long)hh * sCh;

    int row0 = blockIdx.y << 7;
    int col0 = blockIdx.x << 7;
    if (causal_skip && col0 > row0 + 127) return;

    int kEff = Kd;
    if (k_limit) { int lim = row0 + 128; if (lim < kEff) kEff = lim; }

    __shared__ float As[8][132];   // padded: conflict-free transposed stores
    __shared__ float Bs[8][132];

    int tid = threadIdx.x;
    int tx = tid & 15, ty = tid >> 4;

    float acc[8][8];
#pragma unroll
    for (int i = 0; i < 8; i++)
#pragma unroll
        for (int j = 0; j < 8; j++) acc[i][j] = 0.f;

    for (int k0 = 0; k0 < kEff; k0 += 8) {
        // load A tile (128 rows x 8 k), store transposed As[k][m]
#pragma unroll
        for (int l = 0; l < 4; l++) {
            int idx = tid + (l << 8);
            int m = idx >> 3, k = idx & 7;
            int gm = row0 + m, gk = k0 + k;
            float v = 0.f;
            if (gm < M && gk < Kd) v = A[(long)gm * lda + gk];
            As[k][m] = v;
        }
        // load B tile -> Bs[k][n]
#pragma unroll
        for (int l = 0; l < 4; l++) {
            int idx = tid + (l << 8);
            if (TB) {
                int n = idx >> 3, k = idx & 7;
                int gn = col0 + n, gk = k0 + k;
                float v = 0.f;
                if (gn < N && gk < Kd) v = B[(long)gn * ldb + gk];
                Bs[k][n] = v;
            } else {
                int k = idx >> 7, n = idx & 127;
                int gk = k0 + k, gn = col0 + n;
                float v = 0.f;
                if (gk < Kd && gn < N) v = B[(long)gk * ldb + gn];
                Bs[k][n] = v;
            }
        }
        __syncthreads();

#pragma unroll
        for (int kk = 0; kk < 8; kk++) {
            float a[8], b[8];
            *(float4*)&a[0] = *(const float4*)&As[kk][(ty << 3) + 0];
            *(float4*)&a[4] = *(const float4*)&As[kk][(ty << 3) + 4];
            *(float4*)&b[0] = *(const float4*)&Bs[kk][(tx << 3) + 0];
            *(float4*)&b[4] = *(const float4*)&Bs[kk][(tx << 3) + 4];
#pragma unroll
            for (int i = 0; i < 8; i++)
#pragma unroll
                for (int j = 0; j < 8; j++)
                    acc[i][j] = fmaf(a[i], b[j], acc[i][j]);
        }
        __syncthreads();
    }

#pragma unroll
    for (int i = 0; i < 8; i++) {
        int gm = row0 + (ty << 3) + i;
        if (gm >= M) continue;
#pragma unroll
        for (int j = 0; j < 8; j++) {
            int gn = col0 + (tx << 3) + j;
            if (gn >= N) continue;
            long off = (long)gm * ldc + gn;
            float r = alpha * acc[i][j];
            if (beta != 0.f) r += beta * C[off];
            C[off] = r;
        }
    }
}

// ---------------------------------------------------------------------------
// fp64-accumulated GEMM (C = A * B^T), A:[M,K] lda, B:[N,K] ldb, C:[M,N] ldc.
// Batched over grid.z (stride sAb / sCb; B shared). Used only for the small
// t1/query chain so top-k rescoring inputs are exactly rounded (cheap).
// ---------------------------------------------------------------------------
__global__ __launch_bounds__(256)
void gemm_f64acc(int M, int N, int Kd,
                 const float* __restrict__ A, int lda, long sAb,
                 const float* __restrict__ B, int ldb,
                 float* __restrict__ C, int ldc, long sCb)
{
    int b = blockIdx.z;
    A += (long)b * sAb;
    C += (long)b * sCb;

    int row0 = blockIdx.y << 6;
    int col0 = blockIdx.x << 6;

    __shared__ float As[8][68];
    __shared__ float Bs[8][68];

    int tid = threadIdx.x;
    int tx = tid & 15, ty = tid >> 4;

    double acc[4][4];
#pragma unroll
    for (int i = 0; i < 4; i++)
#pragma unroll
        for (int j = 0; j < 4; j++) acc[i][j] = 0.0;

    for (int k0 = 0; k0 < Kd; k0 += 8) {
#pragma unroll
        for (int l = 0; l < 2; l++) {
            int idx = tid + (l << 8);
            int m = idx >> 3, k = idx & 7;
            int gm = row0 + m, gk = k0 + k;
            As[k][m] = (gm < M && gk < Kd) ? A[(long)gm * lda + gk] : 0.f;
            int gn = col0 + m;
            Bs[k][m] = (gn < N && gk < Kd) ? B[(long)gn * ldb + gk] : 0.f;
        }
        __syncthreads();

#pragma unroll
        for (int kk = 0; kk < 8; kk++) {
            float a[4], bb[4];
#pragma unroll
            for (int i = 0; i < 4; i++) a[i]  = As[kk][(ty << 2) + i];
#pragma unroll
            for (int j = 0; j < 4; j++) bb[j] = Bs[kk][(tx << 2) + j];
#pragma unroll
            for (int i = 0; i < 4; i++)
#pragma unroll
                for (int j = 0; j < 4; j++)
                    acc[i][j] = fma((double)a[i], (double)bb[j], acc[i][j]);
        }
        __syncthreads();
    }

#pragma unroll
    for (int i = 0; i < 4; i++) {
        int gm = row0 + (ty << 2) + i;
        if (gm >= M) continue;
#pragma unroll
        for (int j = 0; j < 4; j++) {
            int gn = col0 + (tx << 2) + j;
            if (gn >= N) continue;
            C[(long)gm * ldc + gn] = (float)acc[i][j];
        }
    }
}

// ---------------------------------------------------------------------------
// Causal row softmax on S[row, :T]; valid cols j <= q (q = row % L).
// Masked cols written as exact 0 (matches exp(finfo.min - max) == 0).
// ---------------------------------------------------------------------------
__global__ void causal_softmax_k(float* __restrict__ S, int L, int T)
{
    long row = blockIdx.x;
    int q = (int)(row % L);
    float* p = S + row * (long)T;
    int n = q + 1;
    int tid = threadIdx.x;
    __shared__ float red[32];

    float m = -INFINITY;
    for (int j = tid; j < n; j += blockDim.x) m = fmaxf(m, p[j]);
#pragma unroll
    for (int o = 16; o; o >>= 1) m = fmaxf(m, __shfl_xor_sync(0xffffffffu, m, o));
    if ((tid & 31) == 0) red[tid >> 5] = m;
    __syncthreads();
    if (tid < 32) {
        float v = (tid < (int)(blockDim.x >> 5)) ? red[tid] : -INFINITY;
#pragma unroll
        for (int o = 16; o; o >>= 1) v = fmaxf(v, __shfl_xor_sync(0xffffffffu, v, o));
        if (tid == 0) red[0] = v;
    }
    __syncthreads();
    m = red[0];
    __syncthreads();

    float s = 0.f;
    for (int j = tid; j < n; j += blockDim.x) {
        float e = expf(p[j] - m);
        p[j] = e;
        s += e;
    }
#pragma unroll
    for (int o = 16; o; o >>= 1) s += __shfl_xor_sync(0xffffffffu, s, o);
    if ((tid & 31) == 0) red[tid >> 5] = s;
    __syncthreads();
    if (tid < 32) {
        float v = (tid < (int)(blockDim.x >> 5)) ? red[tid] : 0.f;
#pragma unroll
        for (int o = 16; o; o >>= 1) v += __shfl_xor_sync(0xffffffffu, v, o);
        if (tid == 0) red[0] = v;
    }
    __syncthreads();
    float inv = 1.f / red[0];
    for (int j = tid; j < n; j += blockDim.x) p[j] *= inv;
    for (int j = n + tid; j < T; j += blockDim.x) p[j] = 0.f;
}

// ---------------------------------------------------------------------------
// Top-4 with fp64 refinement.
// Phase 1: per-thread top-4 over its 256-elem stripe of the fp32 sim row.
// Phase 2: serial top-16 fp32 candidates (tie-break lower index).
// Phase 3: fp64-rescore the 16 candidates (query . key), cast to fp32 —
//          reproduces the exactly-rounded selection values.
// Phase 4: top-4 of the rescored values (tie-break lower index).
// ---------------------------------------------------------------------------
__global__ __launch_bounds__(256)
void topk4_refine_k(const float* __restrict__ sim,
                    const float* __restrict__ qry,
                    const float* __restrict__ keys,
                    int* __restrict__ out)
{
    long row = blockIdx.x;              // 0 .. BATCH*NTOK-1
    int b   = (int)(row >> 9);          // row / NTOK
    int tok = (int)(row & (NTOK - 1));
    const float* p = sim + row * (long)NIDX;
    int tid = threadIdx.x;              // 256

    // ---- Phase 1: per-thread top-4 over stripe ----
    float v0 = -INFINITY, v1 = -INFINITY, v2 = -INFINITY, v3 = -INFINITY;
    int   i0 = 0x7fffffff, i1 = 0x7fffffff, i2 = 0x7fffffff, i3 = 0x7fffffff;

    for (int j = tid; j < NIDX; j += 256) {
        float x = p[j];
        if (x > v3 || (x == v3 && j < i3)) {
            if (x > v0 || (x == v0 && j < i0)) {
                v3 = v2; i3 = i2; v2 = v1; i2 = i1; v1 = v0; i1 = i0; v0 = x; i0 = j;
            } else if (x > v1 || (x == v1 && j < i1)) {
                v3 = v2; i3 = i2; v2 = v1; i2 = i1; v1 = x; i1 = j;
            } else if (x > v2 || (x == v2 && j < i2)) {
                v3 = v2; i3 = i2; v2 = x; i2 = j;
            } else {
                v3 = x; i3 = j;
            }
        }
    }

    __shared__ float sv[1024];
    __shared__ int   si[1024];
    sv[tid * 4 + 0] = v0; si[tid * 4 + 0] = i0;
    sv[tid * 4 + 1] = v1; si[tid * 4 + 1] = i1;
    sv[tid * 4 + 2] = v2; si[tid * 4 + 2] = i2;
    sv[tid * 4 + 3] = v3; si[tid * 4 + 3] = i3;
    __syncthreads();

    // ---- Phase 2: serial top-16 candidates ----
    __shared__ int   cidx[16];
    __shared__ float cval[16];
    if (tid == 0) {
        for (int r = 0; r < 16; r++) {
            float best = -INFINITY; int bid = 0x7fffffff; int bp = -1;
            for (int i = 0; i < 1024; i++) {
                float x = sv[i];
                if (x > best || (x == best && si[i] < bid)) { best = x; bid = si[i]; bp = i; }
            }
            cidx[r] = bid;
            sv[bp] = -INFINITY; si[bp] = 0x7fffffff;
        }
    }
    __syncthreads();

    // ---- Phase 3: fp64 rescore of 16 candidates (half-warp per candidate) ----
    {
        int warp = tid >> 5, lane = tid & 31;
        int c = (warp << 1) + (lane >> 4);   // 0..15
        int l = lane & 15;
        const float* qrow = qry + ((long)b * SEQ + tok) * IDXD;
        const float* krow = keys + (long)cidx[c] * IDXD;
        double s = 0.0;
        for (int t = l; t < IDXD; t += 16)
            s = fma((double)qrow[t], (double)krow[t], s);
#pragma unroll
        for (int o = 8; o; o >>= 1) s += __shfl_xor_sync(0xffffffffu, s, o, 16);
        if (l == 0) cval[c] = (float)s;      // exactly-rounded fp32 sim value
    }
    __syncthreads();

    // ---- Phase 4: top-4 of rescored values ----
    if (tid == 0) {
        float lv[16]; int li[16];
#pragma unroll
        for (int i = 0; i < 16; i++) { lv[i] = cval[i]; li[i] = cidx[i]; }
        for (int r = 0; r < TOPK; r++) {
            float best = -INFINITY; int bid = 0x7fffffff; int bp = -1;
#pragma unroll
            for (int i = 0; i < 16; i++) {
                float x = lv[i];
                if (x > best || (x == best && li[i] < bid)) { best = x; bid = li[i]; bp = i; }
            }
            out[row * TOPK + r] = bid;
            lv[bp] = -INFINITY; li[bp] = 0x7fffffff;
        }
    }
}

// ---------------------------------------------------------------------------
// Gather adapter K/V rows: aK[b, j, :] = index_keys[top_idx[b, j/4, j%4]]
// ---------------------------------------------------------------------------
__global__ void gather_k(const int* __restrict__ tidx,
                         const float* __restrict__ keys,
                         const float* __restrict__ vals,
                         float* __restrict__ aK, float* __restrict__ aV)
{
    int blk = blockIdx.x;              // b*2048 + j
    int b = blk >> 11;
    int j = blk & 2047;
    int id = tidx[((b * NTOK + (j >> 2)) << 2) + (j & 3)];
    const float4* ks = (const float4*)(keys + (long)id * IDXD);
    const float4* vs = (const float4*)(vals + (long)id * IDXD);
    float4* dk = (float4*)(aK + (long)blk * IDXD);
    float4* dv = (float4*)(aV + (long)blk * IDXD);
    int t = threadIdx.x;               // 128 threads * float4 = 512 floats
    dk[t] = ks[t];
    dv[t] = vs[t];
}

// ---------------------------------------------------------------------------
// Host launch
// ---------------------------------------------------------------------------
extern "C" void kernel_launch(void* const* d_in, const int* in_sizes, int n_in,
                              void* d_out, int out_size)
{
    const float* hs    = (const float*)d_in[0];
    const float* Wq    = (const float*)d_in[1];
    const float* Wk    = (const float*)d_in[2];
    const float* Wv    = (const float*)d_in[3];
    const float* Wo    = (const float*)d_in[4];
    const float* q_in  = (const float*)d_in[5];
    const float* q_out = (const float*)d_in[6];
    const float* v_in  = (const float*)d_in[7];
    const float* v_out = (const float*)d_in[8];
    const float* ikeys = (const float*)d_in[9];
    const float* ivals = (const float*)d_in[10];
    float* out = (float*)d_out;

    void* p;
    cudaGetSymbolAddress(&p, g_Q);      float* Qb   = (float*)p;
    cudaGetSymbolAddress(&p, g_K);      float* Kb   = (float*)p;
    cudaGetSymbolAddress(&p, g_V);      float* Vb   = (float*)p;
    cudaGetSymbolAddress(&p, g_attn);   float* Ab   = (float*)p;
    cudaGetSymbolAddress(&p, g_scores); float* Sb   = (float*)p;
    cudaGetSymbolAddress(&p, g_t1);     float* t1   = (float*)p;
    cudaGetSymbolAddress(&p, g_query);  float* qry  = (float*)p;
    cudaGetSymbolAddress(&p, g_sim);    float* simb = (float*)p;
    cudaGetSymbolAddress(&p, g_topidx); int*   topi = (int*)p;
    cudaGetSymbolAddress(&p, g_aK);     float* aK   = (float*)p;
    cudaGetSymbolAddress(&p, g_aV);     float* aV   = (float*)p;
    cudaGetSymbolAddress(&p, g_sc2);    float* sc2  = (float*)p;
    cudaGetSymbolAddress(&p, g_mome);   float* mome = (float*)p;
    cudaGetSymbolAddress(&p, g_t2);     float* t2   = (float*)p;

    const int MS = BATCH * SEQ;                        // 8192
    const float scale_base = 1.0f / sqrtf((float)HD);  // 1/sqrt(128)
    const float scale_adpt = 1.0f / sqrtf((float)IDXD);// 1/sqrt(512)
    dim3 blk(256);

    // 1) Q/K/V projections: [8192,2048] = hs @ W^T
    gemm_tile<true><<<dim3(HID / 128, MS / 128, 1), blk>>>(MS, HID, HID, 1.f, 0.f,
        hs, HID, 0, 0, Wq, HID, 0, 0, Qb, HID, 0, 0, 1, 0, 0);
    gemm_tile<true><<<dim3(HID / 128, MS / 128, 1), blk>>>(MS, HID, HID, 1.f, 0.f,
        hs, HID, 0, 0, Wk, HID, 0, 0, Kb, HID, 0, 0, 1, 0, 0);
    gemm_tile<true><<<dim3(HID / 128, MS / 128, 1), blk>>>(MS, HID, HID, 1.f, 0.f,
        hs, HID, 0, 0, Wv, HID, 0, 0, Vb, HID, 0, 0, 1, 0, 0);

    // 2) base scores (batched over b,h), causal tile-skip
    gemm_tile<true><<<dim3(SEQ / 128, SEQ / 128, BATCH * NHEAD), blk>>>(
        SEQ, SEQ, HD, scale_base, 0.f,
        Qb, HID, (long)SEQ * HID, HD,
        Kb, HID, (long)SEQ * HID, HD,
        Sb, SEQ, (long)NHEAD * SEQ * SEQ, (long)SEQ * SEQ,
        NHEAD, 1, 0);

    // 3) causal softmax
    causal_softmax_k<<<BATCH * NHEAD * SEQ, 256>>>(Sb, SEQ, SEQ);

    // 4) AV: attn_out = P @ V (NN, causal K-limit)
    gemm_tile<false><<<dim3(1, SEQ / 128, BATCH * NHEAD), blk>>>(
        SEQ, HD, SEQ, 1.f, 0.f,
        Sb, SEQ, (long)NHEAD * SEQ * SEQ, (long)SEQ * SEQ,
        Vb, HID, (long)SEQ * HID, HD,
        Ab, HID, (long)SEQ * HID, HD,
        NHEAD, 0, 1);

    // 5) out = attn_out @ Wo^T
    gemm_tile<true><<<dim3(HID / 128, MS / 128, 1), blk>>>(MS, HID, HID, 1.f, 0.f,
        Ab, HID, 0, 0, Wo, HID, 0, 0, out, HID, 0, 0, 1, 0, 0);

    // 6) t1 = hs @ q_in^T   [8192,64]  (fp64 accumulate: feeds top-k chain)
    gemm_f64acc<<<dim3(RNK / 64, MS / 64, 1), blk>>>(MS, RNK, HID,
        hs, HID, 0, q_in, HID, t1, RNK, 0);

    // 7) query = t1 @ q_out^T   [8192,512]  (fp64 accumulate)
    gemm_f64acc<<<dim3(IDXD / 64, MS / 64, 1), blk>>>(MS, IDXD, RNK,
        t1, RNK, 0, q_out, RNK, qry, IDXD, 0);

    // 8) sim = query[:512 tokens/batch] @ index_keys^T  (fast fp32, batched)
    gemm_tile<true><<<dim3(NIDX / 128, NTOK / 128, BATCH), blk>>>(
        NTOK, NIDX, IDXD, 1.f, 0.f,
        qry, IDXD, (long)SEQ * IDXD, 0,
        ikeys, IDXD, 0, 0,
        simb, NIDX, (long)NTOK * NIDX, 0,
        1, 0, 0);

    // 9) top-4 per row with fp64 candidate rescoring
    topk4_refine_k<<<BATCH * NTOK, 256>>>(simb, qry, ikeys, topi);

    // 10) gather adapter K/V
    gather_k<<<BATCH * SEQ, 128>>>(topi, ikeys, ivals, aK, aV);

    // 11) adapter scores = query @ aK^T (batched over b, causal tile-skip)
    gemm_tile<true><<<dim3(SEQ / 128, SEQ / 128, BATCH), blk>>>(
        SEQ, SEQ, IDXD, scale_adpt, 0.f,
        qry, IDXD, (long)SEQ * IDXD, 0,
        aK, IDXD, (long)SEQ * IDXD, 0,
        sc2, SEQ, (long)SEQ * SEQ, 0,
        1, 1, 0);

    // 12) causal softmax
    causal_softmax_k<<<BATCH * SEQ, 256>>>(sc2, SEQ, SEQ);

    // 13) mome_attn = P @ aV (NN, causal K-limit)
    gemm_tile<false><<<dim3(IDXD / 128, SEQ / 128, BATCH), blk>>>(
        SEQ, IDXD, SEQ, 1.f, 0.f,
        sc2, SEQ, (long)SEQ * SEQ, 0,
        aV, IDXD, (long)SEQ * IDXD, 0,
        mome, IDXD, (long)SEQ * IDXD, 0,
        1, 0, 1);

    // 14) t2 = mome @ v_in^T   [8192,64]
    gemm_tile<true><<<dim3(1, MS / 128, 1), blk>>>(MS, RNK, IDXD, 1.f, 0.f,
        mome, IDXD, 0, 0, v_in, IDXD, 0, 0, t2, RNK, 0, 0, 1, 0, 0);

    // 15) out += R * (t2 @ v_out^T)
    gemm_tile<true><<<dim3(HID / 128, MS / 128, 1), blk>>>(MS, HID, RNK,
        (float)RNK, 1.f,
        t2, RNK, 0, 0, v_out, RNK, 0, 0, out, HID, 0, 0, 1, 0, 0);
}

// round 7
// speedup vs baseline: 10.8890x; 1.1784x over previous
#include <cuda_runtime.h>
#include <math.h>

// ---------------------------------------------------------------------------
// Problem constants
// ---------------------------------------------------------------------------
#define BATCH 4
#define SEQ   2048
#define HID   2048
#define NHEAD 16
#define HD    128
#define RNK   64
#define IDXD  512
#define NIDX  65536
#define TOPK  4
#define NTOK  512          // only first 512 tokens/batch ever attended in adapter

// ---------------------------------------------------------------------------
// Scratch (device globals; no allocation allowed)
// ---------------------------------------------------------------------------
__device__ float g_Q[(size_t)BATCH * SEQ * HID];
__device__ float g_K[(size_t)BATCH * SEQ * HID];
__device__ float g_V[(size_t)BATCH * SEQ * HID];
__device__ float g_attn[(size_t)BATCH * SEQ * HID];
__device__ float g_scores[(size_t)BATCH * NHEAD * SEQ * SEQ];   // 1.07 GB
__device__ float g_t1[(size_t)BATCH * SEQ * RNK];
__device__ float g_query[(size_t)BATCH * SEQ * IDXD];
__device__ float g_sim[(size_t)BATCH * NTOK * NIDX];            // 537 MB (fp32)
__device__ int   g_topidx[BATCH * NTOK * TOPK];
__device__ float g_aK[(size_t)BATCH * SEQ * IDXD];
__device__ float g_aV[(size_t)BATCH * SEQ * IDXD];
__device__ float g_sc2[(size_t)BATCH * SEQ * SEQ];
__device__ float g_mome[(size_t)BATCH * SEQ * IDXD];
__device__ float g_t2[(size_t)BATCH * SEQ * RNK];

// ---------------------------------------------------------------------------
// TF32 helpers (3xTF32 fp32 emulation: a = hi + lo, error ~2^-22 per product)
// ---------------------------------------------------------------------------
__device__ __forceinline__ float tf32r(float x)
{
    unsigned int u;
    asm("cvt.rna.tf32.f32 %0, %1;" : "=r"(u) : "f"(x));
    return __uint_as_float(u);
}

__device__ __forceinline__ void mma_tf32(float* c, const float* a, const float* b)
{
    asm volatile(
        "mma.sync.aligned.m16n8k8.row.col.f32.tf32.tf32.f32 "
        "{%0,%1,%2,%3}, {%4,%5,%6,%7}, {%8,%9}, {%0,%1,%2,%3};"
        : "+f"(c[0]), "+f"(c[1]), "+f"(c[2]), "+f"(c[3])
        : "r"(__float_as_uint(a[0])), "r"(__float_as_uint(a[1])),
          "r"(__float_as_uint(a[2])), "r"(__float_as_uint(a[3])),
          "r"(__float_as_uint(b[0])), "r"(__float_as_uint(b[1])));
}

// ---------------------------------------------------------------------------
// Tensor-core GEMM (3xTF32, fp32-equivalent accuracy):
//   C = alpha * A * op(B) + beta * C
//   A: [M, K] row-major. TB=true: B [N,K] -> C = A B^T; TB=false: B [K,N].
// Requirements (all call sites satisfy): M % 128 == 0, K % 16 == 0,
//   N % 8 == 0; for TB=false additionally N % 128 == 0.
// Batched over grid.z (b = z/nh, h = z%nh). causal_skip: drop tiles fully
// above diagonal. k_limit: clamp K to row0+128.
// CTA tile 128x128, 8 warps (2x4), warp tile 64x32, m16n8k8 fragments.
// ---------------------------------------------------------------------------
template<bool TB>
__global__ __launch_bounds__(256)
void gemm_mma(int M, int N, int Kd, float alpha, float beta,
              const float* __restrict__ A, int lda, long sAb, long sAh,
              const float* __restrict__ B, int ldb, long sBb, long sBh,
              float* __restrict__ C, int ldc, long sCb, long sCh,
              int nh, int causal_skip, int k_limit)
{
    int z  = blockIdx.z;
    int bb = z / nh, hh = z - bb * nh;
    A += (long)bb * sAb + (long)hh * sAh;
    B += (long)bb * sBb + (long)hh * sBh;
    C += (long)bb * sCb + (long)hh * sCh;

    int row0 = blockIdx.y << 7;
    int col0 = blockIdx.x << 7;
    if (causal_skip && col0 > row0 + 127) return;

    int kEff = Kd;
    if (k_limit) { int lim = row0 + 128; if (lim < kEff) kEff = lim; }

    // padded stride 20: fragment reads hit banks (20*g + k) % 32, all distinct
    __shared__ float Ah[128][20], Al[128][20];
    __shared__ float Bh[128][20], Bl[128][20];

    int tid  = threadIdx.x;
    int warp = tid >> 5, lane = tid & 31;
    int wm = warp & 1;          // 0..1  -> m offset 0/64
    int wn = warp >> 1;         // 0..3  -> n offset 0/32/64/96
    int grp = lane >> 2;        // 0..7
    int tig = lane & 3;         // 0..3

    float acc[16][4];
#pragma unroll
    for (int f = 0; f < 16; f++)
#pragma unroll
        for (int r = 0; r < 4; r++) acc[f][r] = 0.f;

    for (int k0 = 0; k0 < kEff; k0 += 16) {
        // ---- fill A tile: 128 rows x 16 k (2 float4 per thread) ----
#pragma unroll
        for (int s = 0; s < 2; s++) {
            int id = (tid << 1) + s;            // 0..511 float4 slots
            int m = id >> 2, kk = (id & 3) << 2;
            float4 v = *(const float4*)(A + (long)(row0 + m) * lda + (k0 + kk));
            Ah[m][kk + 0] = tf32r(v.x); Al[m][kk + 0] = tf32r(v.x - tf32r(v.x));
            Ah[m][kk + 1] = tf32r(v.y); Al[m][kk + 1] = tf32r(v.y - tf32r(v.y));
            Ah[m][kk + 2] = tf32r(v.z); Al[m][kk + 2] = tf32r(v.z - tf32r(v.z));
            Ah[m][kk + 3] = tf32r(v.w); Al[m][kk + 3] = tf32r(v.w - tf32r(v.w));
        }
        // ---- fill B tile as Bs[n][k] ----
        if (TB) {
#pragma unroll
            for (int s = 0; s < 2; s++) {
                int id = (tid << 1) + s;
                int n = id >> 2, kk = (id & 3) << 2;
                int gn = col0 + n;
                float4 v = make_float4(0.f, 0.f, 0.f, 0.f);
                if (gn < N) v = *(const float4*)(B + (long)gn * ldb + (k0 + kk));
                Bh[n][kk + 0] = tf32r(v.x); Bl[n][kk + 0] = tf32r(v.x - tf32r(v.x));
                Bh[n][kk + 1] = tf32r(v.y); Bl[n][kk + 1] = tf32r(v.y - tf32r(v.y));
                Bh[n][kk + 2] = tf32r(v.z); Bl[n][kk + 2] = tf32r(v.z - tf32r(v.z));
                Bh[n][kk + 3] = tf32r(v.w); Bl[n][kk + 3] = tf32r(v.w - tf32r(v.w));
            }
        } else {
            // B is [K, N]; N % 128 == 0 at all TB=false call sites
#pragma unroll
            for (int s = 0; s < 8; s++) {
                int id = (s << 8) + tid;        // 0..2047
                int kk = id >> 7, n = id & 127;
                float v = B[(long)(k0 + kk) * ldb + (col0 + n)];
                float h = tf32r(v);
                Bh[n][kk] = h; Bl[n][kk] = tf32r(v - h);
            }
        }
        __syncthreads();

#pragma unroll
        for (int k8 = 0; k8 < 16; k8 += 8) {
            // load A fragments (hi and lo) for this k8
            float ah[4][4], al[4][4];
#pragma unroll
            for (int i = 0; i < 4; i++) {
                int r = (wm << 6) + (i << 4) + grp;
                int kc = k8 + tig;
                ah[i][0] = Ah[r][kc];     ah[i][1] = Ah[r + 8][kc];
                ah[i][2] = Ah[r][kc + 4]; ah[i][3] = Ah[r + 8][kc + 4];
                al[i][0] = Al[r][kc];     al[i][1] = Al[r + 8][kc];
                al[i][2] = Al[r][kc + 4]; al[i][3] = Al[r + 8][kc + 4];
            }
            // pass 0: hi*hi   pass 1: hi*lo   pass 2: lo*hi
#pragma unroll
            for (int p = 0; p < 3; p++) {
#pragma unroll
                for (int j = 0; j < 4; j++) {
                    int n = (wn << 5) + (j << 3) + grp;
                    int kc = k8 + tig;
                    float bf[2];
                    if (p == 1) { bf[0] = Bl[n][kc]; bf[1] = Bl[n][kc + 4]; }
                    else        { bf[0] = Bh[n][kc]; bf[1] = Bh[n][kc + 4]; }
#pragma unroll
                    for (int i = 0; i < 4; i++) {
                        if (p == 2) mma_tf32(acc[i * 4 + j], al[i], bf);
                        else        mma_tf32(acc[i * 4 + j], ah[i], bf);
                    }
                }
            }
        }
        __syncthreads();
    }

    // ---- epilogue ----
#pragma unroll
    for (int i = 0; i < 4; i++) {
#pragma unroll
        for (int j = 0; j < 4; j++) {
            float* c = acc[i * 4 + j];
            int gm = row0 + (wm << 6) + (i << 4) + grp;
            int gn = col0 + (wn << 5) + (j << 3) + (tig << 1);
            if (gn < N) {     // N % 8 == 0 -> gn+1 < N too
                long o0 = (long)gm * ldc + gn;
                long o1 = (long)(gm + 8) * ldc + gn;
                float2 r0, r1;
                r0.x = alpha * c[0]; r0.y = alpha * c[1];
                r1.x = alpha * c[2]; r1.y = alpha * c[3];
                if (beta != 0.f) {
                    float2 p0 = *(float2*)(C + o0);
                    float2 p1 = *(float2*)(C + o1);
                    r0.x += beta * p0.x; r0.y += beta * p0.y;
                    r1.x += beta * p1.x; r1.y += beta * p1.y;
                }
                *(float2*)(C + o0) = r0;
                *(float2*)(C + o1) = r1;
            }
        }
    }
}

// ---------------------------------------------------------------------------
// fp64-accumulated GEMM (C = A * B^T) — small t1/query chain only, so top-k
// rescoring inputs are exactly rounded.
// ---------------------------------------------------------------------------
__global__ __launch_bounds__(256)
void gemm_f64acc(int M, int N, int Kd,
                 const float* __restrict__ A, int lda, long sAb,
                 const float* __restrict__ B, int ldb,
                 float* __restrict__ C, int ldc, long sCb)
{
    int b = blockIdx.z;
    A += (long)b * sAb;
    C += (long)b * sCb;

    int row0 = blockIdx.y << 6;
    int col0 = blockIdx.x << 6;

    __shared__ float As[8][68];
    __shared__ float Bs[8][68];

    int tid = threadIdx.x;
    int tx = tid & 15, ty = tid >> 4;

    double acc[4][4];
#pragma unroll
    for (int i = 0; i < 4; i++)
#pragma unroll
        for (int j = 0; j < 4; j++) acc[i][j] = 0.0;

    for (int k0 = 0; k0 < Kd; k0 += 8) {
#pragma unroll
        for (int l = 0; l < 2; l++) {
            int idx = tid + (l << 8);
            int m = idx >> 3, k = idx & 7;
            int gm = row0 + m, gk = k0 + k;
            As[k][m] = (gm < M && gk < Kd) ? A[(long)gm * lda + gk] : 0.f;
            int gn = col0 + m;
            Bs[k][m] = (gn < N && gk < Kd) ? B[(long)gn * ldb + gk] : 0.f;
        }
        __syncthreads();

#pragma unroll
        for (int kk = 0; kk < 8; kk++) {
            float a[4], bb[4];
#pragma unroll
            for (int i = 0; i < 4; i++) a[i]  = As[kk][(ty << 2) + i];
#pragma unroll
            for (int j = 0; j < 4; j++) bb[j] = Bs[kk][(tx << 2) + j];
#pragma unroll
            for (int i = 0; i < 4; i++)
#pragma unroll
                for (int j = 0; j < 4; j++)
                    acc[i][j] = fma((double)a[i], (double)bb[j], acc[i][j]);
        }
        __syncthreads();
    }

#pragma unroll
    for (int i = 0; i < 4; i++) {
        int gm = row0 + (ty << 2) + i;
        if (gm >= M) continue;
#pragma unroll
        for (int j = 0; j < 4; j++) {
            int gn = col0 + (tx << 2) + j;
            if (gn >= N) continue;
            C[(long)gm * ldc + gn] = (float)acc[i][j];
        }
    }
}

// ---------------------------------------------------------------------------
// Causal row softmax on S[row, :T]; valid cols j <= q (q = row % L).
// ---------------------------------------------------------------------------
__global__ void causal_softmax_k(float* __restrict__ S, int L, int T)
{
    long row = blockIdx.x;
    int q = (int)(row % L);
    float* p = S + row * (long)T;
    int n = q + 1;
    int tid = threadIdx.x;
    __shared__ float red[32];

    float m = -INFINITY;
    for (int j = tid; j < n; j += blockDim.x) m = fmaxf(m, p[j]);
#pragma unroll
    for (int o = 16; o; o >>= 1) m = fmaxf(m, __shfl_xor_sync(0xffffffffu, m, o));
    if ((tid & 31) == 0) red[tid >> 5] = m;
    __syncthreads();
    if (tid < 32) {
        float v = (tid < (int)(blockDim.x >> 5)) ? red[tid] : -INFINITY;
#pragma unroll
        for (int o = 16; o; o >>= 1) v = fmaxf(v, __shfl_xor_sync(0xffffffffu, v, o));
        if (tid == 0) red[0] = v;
    }
    __syncthreads();
    m = red[0];
    __syncthreads();

    float s = 0.f;
    for (int j = tid; j < n; j += blockDim.x) {
        float e = expf(p[j] - m);
        p[j] = e;
        s += e;
    }
#pragma unroll
    for (int o = 16; o; o >>= 1) s += __shfl_xor_sync(0xffffffffu, s, o);
    if ((tid & 31) == 0) red[tid >> 5] = s;
    __syncthreads();
    if (tid < 32) {
        float v = (tid < (int)(blockDim.x >> 5)) ? red[tid] : 0.f;
#pragma unroll
        for (int o = 16; o; o >>= 1) v += __shfl_xor_sync(0xffffffffu, v, o);
        if (tid == 0) red[0] = v;
    }
    __syncthreads();
    float inv = 1.f / red[0];
    for (int j = tid; j < n; j += blockDim.x) p[j] *= inv;
    for (int j = n + tid; j < T; j += blockDim.x) p[j] = 0.f;
}

// ---------------------------------------------------------------------------
// Top-4 with fp64 refinement (phases: stripe top-4 -> serial top-16 ->
// fp64 rescore -> top-4). Tie-break: lower index (matches jax.lax.top_k).
// ---------------------------------------------------------------------------
__global__ __launch_bounds__(256)
void topk4_refine_k(const float* __restrict__ sim,
                    const float* __restrict__ qry,
                    const float* __restrict__ keys,
                    int* __restrict__ out)
{
    long row = blockIdx.x;
    int b   = (int)(row >> 9);
    int tok = (int)(row & (NTOK - 1));
    const float* p = sim + row * (long)NIDX;
    int tid = threadIdx.x;

    float v0 = -INFINITY, v1 = -INFINITY, v2 = -INFINITY, v3 = -INFINITY;
    int   i0 = 0x7fffffff, i1 = 0x7fffffff, i2 = 0x7fffffff, i3 = 0x7fffffff;

    for (int j = tid; j < NIDX; j += 256) {
        float x = p[j];
        if (x > v3 || (x == v3 && j < i3)) {
            if (x > v0 || (x == v0 && j < i0)) {
                v3 = v2; i3 = i2; v2 = v1; i2 = i1; v1 = v0; i1 = i0; v0 = x; i0 = j;
            } else if (x > v1 || (x == v1 && j < i1)) {
                v3 = v2; i3 = i2; v2 = v1; i2 = i1; v1 = x; i1 = j;
            } else if (x > v2 || (x == v2 && j < i2)) {
                v3 = v2; i3 = i2; v2 = x; i2 = j;
            } else {
                v3 = x; i3 = j;
            }
        }
    }

    __shared__ float sv[1024];
    __shared__ int   si[1024];
    sv[tid * 4 + 0] = v0; si[tid * 4 + 0] = i0;
    sv[tid * 4 + 1] = v1; si[tid * 4 + 1] = i1;
    sv[tid * 4 + 2] = v2; si[tid * 4 + 2] = i2;
    sv[tid * 4 + 3] = v3; si[tid * 4 + 3] = i3;
    __syncthreads();

    __shared__ int   cidx[16];
    __shared__ float cval[16];
    if (tid == 0) {
        for (int r = 0; r < 16; r++) {
            float best = -INFINITY; int bid = 0x7fffffff; int bp = -1;
            for (int i = 0; i < 1024; i++) {
                float x = sv[i];
                if (x > best || (x == best && si[i] < bid)) { best = x; bid = si[i]; bp = i; }
            }
            cidx[r] = bid;
            sv[bp] = -INFINITY; si[bp] = 0x7fffffff;
        }
    }
    __syncthreads();

    {
        int warp = tid >> 5, lane = tid & 31;
        int c = (warp << 1) + (lane >> 4);
        int l = lane & 15;
        const float* qrow = qry + ((long)b * SEQ + tok) * IDXD;
        const float* krow = keys + (long)cidx[c] * IDXD;
        double s = 0.0;
        for (int t = l; t < IDXD; t += 16)
            s = fma((double)qrow[t], (double)krow[t], s);
#pragma unroll
        for (int o = 8; o; o >>= 1) s += __shfl_xor_sync(0xffffffffu, s, o, 16);
        if (l == 0) cval[c] = (float)s;
    }
    __syncthreads();

    if (tid == 0) {
        float lv[16]; int li[16];
#pragma unroll
        for (int i = 0; i < 16; i++) { lv[i] = cval[i]; li[i] = cidx[i]; }
        for (int r = 0; r < TOPK; r++) {
            float best = -INFINITY; int bid = 0x7fffffff; int bp = -1;
#pragma unroll
            for (int i = 0; i < 16; i++) {
                float x = lv[i];
                if (x > best || (x == best && li[i] < bid)) { best = x; bid = li[i]; bp = i; }
            }
            out[row * TOPK + r] = bid;
            lv[bp] = -INFINITY; li[bp] = 0x7fffffff;
        }
    }
}

// ---------------------------------------------------------------------------
// Gather adapter K/V rows
// ---------------------------------------------------------------------------
__global__ void gather_k(const int* __restrict__ tidx,
                         const float* __restrict__ keys,
                         const float* __restrict__ vals,
                         float* __restrict__ aK, float* __restrict__ aV)
{
    int blk = blockIdx.x;
    int b = blk >> 11;
    int j = blk & 2047;
    int id = tidx[((b * NTOK + (j >> 2)) << 2) + (j & 3)];
    const float4* ks = (const float4*)(keys + (long)id * IDXD);
    const float4* vs = (const float4*)(vals + (long)id * IDXD);
    float4* dk = (float4*)(aK + (long)blk * IDXD);
    float4* dv = (float4*)(aV + (long)blk * IDXD);
    int t = threadIdx.x;
    dk[t] = ks[t];
    dv[t] = vs[t];
}

// ---------------------------------------------------------------------------
// Host launch
// ---------------------------------------------------------------------------
extern "C" void kernel_launch(void* const* d_in, const int* in_sizes, int n_in,
                              void* d_out, int out_size)
{
    const float* hs    = (const float*)d_in[0];
    const float* Wq    = (const float*)d_in[1];
    const float* Wk    = (const float*)d_in[2];
    const float* Wv    = (const float*)d_in[3];
    const float* Wo    = (const float*)d_in[4];
    const float* q_in  = (const float*)d_in[5];
    const float* q_out = (const float*)d_in[6];
    const float* v_in  = (const float*)d_in[7];
    const float* v_out = (const float*)d_in[8];
    const float* ikeys = (const float*)d_in[9];
    const float* ivals = (const float*)d_in[10];
    float* out = (float*)d_out;

    void* p;
    cudaGetSymbolAddress(&p, g_Q);      float* Qb   = (float*)p;
    cudaGetSymbolAddress(&p, g_K);      float* Kb   = (float*)p;
    cudaGetSymbolAddress(&p, g_V);      float* Vb   = (float*)p;
    cudaGetSymbolAddress(&p, g_attn);   float* Ab   = (float*)p;
    cudaGetSymbolAddress(&p, g_scores); float* Sb   = (float*)p;
    cudaGetSymbolAddress(&p, g_t1);     float* t1   = (float*)p;
    cudaGetSymbolAddress(&p, g_query);  float* qry  = (float*)p;
    cudaGetSymbolAddress(&p, g_sim);    float* simb = (float*)p;
    cudaGetSymbolAddress(&p, g_topidx); int*   topi = (int*)p;
    cudaGetSymbolAddress(&p, g_aK);     float* aK   = (float*)p;
    cudaGetSymbolAddress(&p, g_aV);     float* aV   = (float*)p;
    cudaGetSymbolAddress(&p, g_sc2);    float* sc2  = (float*)p;
    cudaGetSymbolAddress(&p, g_mome);   float* mome = (float*)p;
    cudaGetSymbolAddress(&p, g_t2);     float* t2   = (float*)p;

    const int MS = BATCH * SEQ;                        // 8192
    const float scale_base = 1.0f / sqrtf((float)HD);
    const float scale_adpt = 1.0f / sqrtf((float)IDXD);
    dim3 blk(256);

    // 1) Q/K/V projections: [8192,2048] = hs @ W^T
    gemm_mma<true><<<dim3(HID / 128, MS / 128, 1), blk>>>(MS, HID, HID, 1.f, 0.f,
        hs, HID, 0, 0, Wq, HID, 0, 0, Qb, HID, 0, 0, 1, 0, 0);
    gemm_mma<true><<<dim3(HID / 128, MS / 128, 1), blk>>>(MS, HID, HID, 1.f, 0.f,
        hs, HID, 0, 0, Wk, HID, 0, 0, Kb, HID, 0, 0, 1, 0, 0);
    gemm_mma<true><<<dim3(HID / 128, MS / 128, 1), blk>>>(MS, HID, HID, 1.f, 0.f,
        hs, HID, 0, 0, Wv, HID, 0, 0, Vb, HID, 0, 0, 1, 0, 0);

    // 2) base scores (batched over b,h), causal tile-skip
    gemm_mma<true><<<dim3(SEQ / 128, SEQ / 128, BATCH * NHEAD), blk>>>(
        SEQ, SEQ, HD, scale_base, 0.f,
        Qb, HID, (long)SEQ * HID, HD,
        Kb, HID, (long)SEQ * HID, HD,
        Sb, SEQ, (long)NHEAD * SEQ * SEQ, (long)SEQ * SEQ,
        NHEAD, 1, 0);

    // 3) causal softmax
    causal_softmax_k<<<BATCH * NHEAD * SEQ, 256>>>(Sb, SEQ, SEQ);

    // 4) AV: attn_out = P @ V (NN, causal K-limit)
    gemm_mma<false><<<dim3(1, SEQ / 128, BATCH * NHEAD), blk>>>(
        SEQ, HD, SEQ, 1.f, 0.f,
        Sb, SEQ, (long)NHEAD * SEQ * SEQ, (long)SEQ * SEQ,
        Vb, HID, (long)SEQ * HID, HD,
        Ab, HID, (long)SEQ * HID, HD,
        NHEAD, 0, 1);

    // 5) out = attn_out @ Wo^T
    gemm_mma<true><<<dim3(HID / 128, MS / 128, 1), blk>>>(MS, HID, HID, 1.f, 0.f,
        Ab, HID, 0, 0, Wo, HID, 0, 0, out, HID, 0, 0, 1, 0, 0);

    // 6) t1 = hs @ q_in^T   [8192,64]  (fp64: feeds top-k chain)
    gemm_f64acc<<<dim3(RNK / 64, MS / 64, 1), blk>>>(MS, RNK, HID,
        hs, HID, 0, q_in, HID, t1, RNK, 0);

    // 7) query = t1 @ q_out^T   [8192,512]  (fp64)
    gemm_f64acc<<<dim3(IDXD / 64, MS / 64, 1), blk>>>(MS, IDXD, RNK,
        t1, RNK, 0, q_out, RNK, qry, IDXD, 0);

    // 8) sim = query[:512 tokens/batch] @ index_keys^T  (3xTF32, batched)
    gemm_mma<true><<<dim3(NIDX / 128, NTOK / 128, BATCH), blk>>>(
        NTOK, NIDX, IDXD, 1.f, 0.f,
        qry, IDXD, (long)SEQ * IDXD, 0,
        ikeys, IDXD, 0, 0,
        simb, NIDX, (long)NTOK * NIDX, 0,
        1, 0, 0);

    // 9) top-4 per row with fp64 candidate rescoring
    topk4_refine_k<<<BATCH * NTOK, 256>>>(simb, qry, ikeys, topi);

    // 10) gather adapter K/V
    gather_k<<<BATCH * SEQ, 128>>>(topi, ikeys, ivals, aK, aV);

    // 11) adapter scores = query @ aK^T (batched over b, causal tile-skip)
    gemm_mma<true><<<dim3(SEQ / 128, SEQ / 128, BATCH), blk>>>(
        SEQ, SEQ, IDXD, scale_adpt, 0.f,
        qry, IDXD, (long)SEQ * IDXD, 0,
        aK, IDXD, (long)SEQ * IDXD, 0,
        sc2, SEQ, (long)SEQ * SEQ, 0,
        1, 1, 0);

    // 12) causal softmax
    causal_softmax_k<<<BATCH * SEQ, 256>>>(sc2, SEQ, SEQ);

    // 13) mome_attn = P @ aV (NN, causal K-limit)
    gemm_mma<false><<<dim3(IDXD / 128, SEQ / 128, BATCH), blk>>>(
        SEQ, IDXD, SEQ, 1.f, 0.f,
        sc2, SEQ, (long)SEQ * SEQ, 0,
        aV, IDXD, (long)SEQ * IDXD, 0,
        mome, IDXD, (long)SEQ * IDXD, 0,
        1, 0, 1);

    // 14) t2 = mome @ v_in^T   [8192,64]
    gemm_mma<true><<<dim3(1, MS / 128, 1), blk>>>(MS, RNK, IDXD, 1.f, 0.f,
        mome, IDXD, 0, 0, v_in, IDXD, 0, 0, t2, RNK, 0, 0, 1, 0, 0);

    // 15) out += R * (t2 @ v_out^T)
    gemm_mma<true><<<dim3(HID / 128, MS / 128, 1), blk>>>(MS, HID, RNK,
        (float)RNK, 1.f,
        t2, RNK, 0, 0, v_out, RNK, 0, 0, out, HID, 0, 0, 1, 0, 0);
}